// round 13
// baseline (speedup 1.0000x reference)
#include <cuda_runtime.h>
#include <math.h>

#define BATCH   4096
#define VOCAB   100000
#define NTRI    3276
#define NPAIR2  351
#define NT4     1121
#define T4E     588     // float4-runs in even-p rows (parity-ordered layout)
#define T2E     182     // pairs in even-p rows
#define XDIM    224     // [0:13] dense, [13:16] zero pad, [16:224] emb (26*8)

typedef unsigned long long ull;

// ---------------- scratch (device globals) ----------------
__device__ __align__(16) float g_V[128 * 26];
__device__ __align__(16) float g_V0c[NPAIR2];    // parity-ordered
__device__ __align__(16) float g_T3[NPAIR2 * 26];
__device__ __align__(16) float4 g_Tc4[NT4];      // parity-ordered
__device__ int   g_runofs[NPAIR2];               // parity-ordered run offsets
__device__ __align__(16) float g_vb[32];
__device__ float g_cadd;
__device__ __align__(16) float g_X[BATCH * XDIM];
__device__ float g_lin[BATCH];
__device__ __align__(16) float g_h1[BATCH * 256];
__device__ __align__(16) float g_h2[BATCH * 128];

// ---------------- packed f32x2 helpers ----------------
__device__ __forceinline__ ull pk2(float lo, float hi) {
    ull r;
    asm("mov.b64 %0, {%1, %2};" : "=l"(r) : "f"(lo), "f"(hi));
    return r;
}
__device__ __forceinline__ ull fma2(ull a, ull b, ull c) {
    ull d;
    asm("fma.rn.f32x2 %0, %1, %2, %3;" : "=l"(d) : "l"(a), "l"(b), "l"(c));
    return d;
}
__device__ __forceinline__ ull mul2(ull a, ull b) {
    ull d;
    asm("mul.rn.f32x2 %0, %1, %2;" : "=l"(d) : "l"(a), "l"(b));
    return d;
}
__device__ __forceinline__ ull add2(ull a, ull b) {
    ull d;
    asm("add.rn.f32x2 %0, %1, %2;" : "=l"(d) : "l"(a), "l"(b));
    return d;
}
__device__ __forceinline__ float2 up2(ull v) {
    float2 f;
    asm("mov.b64 {%0, %1}, %2;" : "=f"(f.x), "=f"(f.y) : "l"(v));
    return f;
}
__device__ __forceinline__ int pidx(int a, int b) {
    return a * 26 - a * (a - 1) / 2 + (b - a);
}

// ================= K1: gather (blocks 0..431)  ||  prepV (blocks 432..463) =====
__global__ __launch_bounds__(256) void k_front(const float* __restrict__ inputs,
                                               const float* __restrict__ emb_tables,
                                               const float* __restrict__ linW,
                                               const float* __restrict__ linb,
                                               const float* __restrict__ W1,
                                               const float* __restrict__ clinW,
                                               const float* __restrict__ b0,
                                               const float* __restrict__ b1) {
    int bx = blockIdx.x;
    if (bx < 416) {
        int t = bx * 256 + threadIdx.x;
        int b = t / 26, f = t - b * 26;
        int idx = (int)inputs[b * 39 + 13 + f];
        const float4* src = (const float4*)(emb_tables + ((size_t)f * VOCAB + idx) * 8);
        float4* dst = (float4*)(g_X + b * XDIM + 16 + f * 8);
        dst[0] = src[0];
        dst[1] = src[1];
    } else if (bx < 432) {
        int b = (bx - 416) * 256 + threadIdx.x;
        const float* row = inputs + b * 39;
        float lin = linb[0];
        #pragma unroll
        for (int k = 0; k < 13; k++) {
            float v = row[k];
            g_X[b * XDIM + k] = v;
            lin = fmaf(v, linW[k], lin);
        }
        g_X[b * XDIM + 13] = 0.f;
        g_X[b * XDIM + 14] = 0.f;
        g_X[b * XDIM + 15] = 0.f;
        #pragma unroll
        for (int k = 13; k < 39; k++) lin = fmaf(row[k], linW[k], lin);
        g_lin[b] = lin;
    } else {
        int t0 = (bx - 432) * 256 + threadIdx.x;
        const int st = 32 * 256;
        float* tc4f = (float*)g_Tc4;
        for (int u = t0; u < NT4 * 4; u += st) tc4f[u] = 0.f;
        for (int u = t0; u < 3328; u += st) {
            float s0 = 0.f, s1 = 0.f, s2 = 0.f, s3 = 0.f;
            #pragma unroll 8
            for (int o = 0; o < 128; o += 4) {
                s0 = fmaf(clinW[128 + o + 0], W1[(o + 0) * 3328 + u], s0);
                s1 = fmaf(clinW[128 + o + 1], W1[(o + 1) * 3328 + u], s1);
                s2 = fmaf(clinW[128 + o + 2], W1[(o + 2) * 3328 + u], s2);
                s3 = fmaf(clinW[128 + o + 3], W1[(o + 3) * 3328 + u], s3);
            }
            g_V[u] = (s0 + s1) + (s2 + s3);
        }
        for (int t2 = t0; t2 < NPAIR2; t2 += st) {
            int p = 0, rem = t2;
            while (rem >= 26 - p) { rem -= 26 - p; p++; }
            int q = p + rem;
            int s4 = (p & 1) ? T4E : 0;
            for (int pp = (p & 1); pp < p; pp += 2)
                for (int qq = pp; qq < 26; qq++) s4 += 7 - (qq >> 2);
            for (int qq = p; qq < q; qq++) s4 += 7 - (qq >> 2);
            g_runofs[t2] = s4;
        }
        if (t0 < 32) {
            float s = 0.f;
            for (int o = t0; o < 128; o += 32)
                s += clinW[o] * b0[o] + clinW[128 + o] * b1[o];
            #pragma unroll
            for (int off = 16; off; off >>= 1) s += __shfl_down_sync(0xffffffffu, s, off);
            if (t0 == 0) g_cadd = 8.f * s;
        }
    }
}

// ================= K2: mlp1 (blocks 0..255)  ||  prepT3+V0c (blocks 256..299) ===
__global__ __launch_bounds__(256) void k_mid(const float* __restrict__ W1,
                                             const float* __restrict__ b1,
                                             const float* __restrict__ W0,
                                             const float* __restrict__ clinW) {
    __shared__ __align__(16) unsigned char smem[24576];
    int blk = blockIdx.x;
    int tid = threadIdx.x;
    if (blk >= 256) {
        int pq = (blk - 256) * 8 + (tid >> 5);
        if (pq >= NPAIR2) return;
        int p = 0, rem = pq;
        while (rem >= 26 - p) { rem -= 26 - p; p++; }
        int q = p + rem;
        int j = tid & 31;
        const float* wp = W0 + p * 26 + q;
        const float* wq = W0 + q * 26 + p;
        bool isV = (j == 26);
        bool isT = (j < 26);
        float a0 = 0.f, a1 = 0.f, a2 = 0.f, a3 = 0.f;
        if (p == q) {
            #pragma unroll 4
            for (int i = 0; i < 128; i += 4) {
                float w0 = __ldg(&wp[(i + 0) * 676]);
                float w1 = __ldg(&wp[(i + 1) * 676]);
                float w2 = __ldg(&wp[(i + 2) * 676]);
                float w3 = __ldg(&wp[(i + 3) * 676]);
                float v0 = isT ? g_V[(i + 0) * 26 + j] : (isV ? clinW[i + 0] : 0.f);
                float v1 = isT ? g_V[(i + 1) * 26 + j] : (isV ? clinW[i + 1] : 0.f);
                float v2 = isT ? g_V[(i + 2) * 26 + j] : (isV ? clinW[i + 2] : 0.f);
                float v3 = isT ? g_V[(i + 3) * 26 + j] : (isV ? clinW[i + 3] : 0.f);
                a0 = fmaf(w0, v0, a0); a1 = fmaf(w1, v1, a1);
                a2 = fmaf(w2, v2, a2); a3 = fmaf(w3, v3, a3);
            }
        } else {
            #pragma unroll 4
            for (int i = 0; i < 128; i += 4) {
                float w0 = __ldg(&wp[(i + 0) * 676]) + __ldg(&wq[(i + 0) * 676]);
                float w1 = __ldg(&wp[(i + 1) * 676]) + __ldg(&wq[(i + 1) * 676]);
                float w2 = __ldg(&wp[(i + 2) * 676]) + __ldg(&wq[(i + 2) * 676]);
                float w3 = __ldg(&wp[(i + 3) * 676]) + __ldg(&wq[(i + 3) * 676]);
                float v0 = isT ? g_V[(i + 0) * 26 + j] : (isV ? clinW[i + 0] : 0.f);
                float v1 = isT ? g_V[(i + 1) * 26 + j] : (isV ? clinW[i + 1] : 0.f);
                float v2 = isT ? g_V[(i + 2) * 26 + j] : (isV ? clinW[i + 2] : 0.f);
                float v3 = isT ? g_V[(i + 3) * 26 + j] : (isV ? clinW[i + 3] : 0.f);
                a0 = fmaf(w0, v0, a0); a1 = fmaf(w1, v1, a1);
                a2 = fmaf(w2, v2, a2); a3 = fmaf(w3, v3, a3);
            }
        }
        float s = (a0 + a1) + (a2 + a3);
        if (isT) g_T3[pq * 26 + j] = s;
        else if (isV) {
            int t2pos = (p & 1) ? T2E : 0;
            for (int pp = (p & 1); pp < p; pp += 2) t2pos += 26 - pp;
            t2pos += q - p;
            g_V0c[t2pos] = s;
        }
        return;
    }
    // mlp1: (4096 x 224)@(224 x 256), relu, f32x2, BM64 BN64
    float* As = (float*)smem;
    ull*   Bs = (ull*)(smem + 8192);
    int b0 = (blk >> 2) * 64, n0 = (blk & 3) * 64;
    int arow = tid & 63, kq = tid >> 6;
    int r0 = (tid & 15) * 4;
    int c0 = (tid >> 4) * 4;
    ull acc[2][4];
    #pragma unroll
    for (int i = 0; i < 2; i++)
        #pragma unroll
        for (int c = 0; c < 4; c++) acc[i][c] = 0ull;

    for (int k0 = 0; k0 < XDIM; k0 += 32) {
        #pragma unroll
        for (int i = 0; i < 2; i++) {
            int kb = kq * 4 + i * 16;
            float4 v = *(const float4*)&g_X[(b0 + arow) * XDIM + k0 + kb];
            As[(kb + 0) * 64 + arow] = v.x;
            As[(kb + 1) * 64 + arow] = v.y;
            As[(kb + 2) * 64 + arow] = v.z;
            As[(kb + 3) * 64 + arow] = v.w;
        }
        #pragma unroll
        for (int i = 0; i < 2; i++) {
            int t4 = tid + i * 256;
            int kk = t4 >> 4, c4 = t4 & 15;
            int krow = k0 + kk;
            float4 w = make_float4(0.f, 0.f, 0.f, 0.f);
            if (krow < 13)       w = *(const float4*)&W1[krow * 256 + n0 + c4 * 4];
            else if (krow >= 16) w = *(const float4*)&W1[(krow - 3) * 256 + n0 + c4 * 4];
            ulonglong2 d0 = {pk2(w.x, w.x), pk2(w.y, w.y)};
            ulonglong2 d1 = {pk2(w.z, w.z), pk2(w.w, w.w)};
            *(ulonglong2*)&Bs[kk * 64 + c4 * 4] = d0;
            *(ulonglong2*)&Bs[kk * 64 + c4 * 4 + 2] = d1;
        }
        __syncthreads();
        #pragma unroll
        for (int kk = 0; kk < 32; kk++) {
            ulonglong2 av = *(const ulonglong2*)&As[kk * 64 + r0];
            ulonglong2 bv0 = *(const ulonglong2*)&Bs[kk * 64 + c0];
            ulonglong2 bv1 = *(const ulonglong2*)&Bs[kk * 64 + c0 + 2];
            acc[0][0] = fma2(av.x, bv0.x, acc[0][0]);
            acc[0][1] = fma2(av.x, bv0.y, acc[0][1]);
            acc[0][2] = fma2(av.x, bv1.x, acc[0][2]);
            acc[0][3] = fma2(av.x, bv1.y, acc[0][3]);
            acc[1][0] = fma2(av.y, bv0.x, acc[1][0]);
            acc[1][1] = fma2(av.y, bv0.y, acc[1][1]);
            acc[1][2] = fma2(av.y, bv1.x, acc[1][2]);
            acc[1][3] = fma2(av.y, bv1.y, acc[1][3]);
        }
        __syncthreads();
    }
    float4 bb = *(const float4*)&b1[n0 + c0];
    #pragma unroll
    for (int rp = 0; rp < 2; rp++) {
        float2 x0 = up2(acc[rp][0]), x1 = up2(acc[rp][1]);
        float2 x2 = up2(acc[rp][2]), x3 = up2(acc[rp][3]);
        int row = b0 + r0 + rp * 2;
        float4 o0 = {fmaxf(x0.x + bb.x, 0.f), fmaxf(x1.x + bb.y, 0.f),
                     fmaxf(x2.x + bb.z, 0.f), fmaxf(x3.x + bb.w, 0.f)};
        float4 o1 = {fmaxf(x0.y + bb.x, 0.f), fmaxf(x1.y + bb.y, 0.f),
                     fmaxf(x2.y + bb.z, 0.f), fmaxf(x3.y + bb.w, 0.f)};
        *(float4*)&g_h1[row * 256 + n0 + c0] = o0;
        *(float4*)&g_h1[(row + 1) * 256 + n0 + c0] = o1;
    }
}

// ================= K3: mlp2 (blocks 0..127)  ||  prepFold (blocks 128..140) =====
__global__ __launch_bounds__(256) void k_back(const float* __restrict__ W2,
                                              const float* __restrict__ b2,
                                              const float* __restrict__ b0cin) {
    __shared__ __align__(16) unsigned char smem[24576];
    int blk = blockIdx.x;
    int tid = threadIdx.x;
    if (blk >= 128) {
        int t = (blk - 128) * 256 + tid;
        if (t < NTRI) {
            int rem = t, p = 0;
            while (true) { int c = (26 - p) * (27 - p) / 2; if (rem < c) break; rem -= c; p++; }
            int q = p;
            while (true) { int c = 26 - q; if (rem < c) break; rem -= c; q++; }
            int j = q + rem;
            float v;
            if (p == q && q == j)
                v = g_T3[pidx(p, p) * 26 + p];
            else if (p == q)
                v = g_T3[pidx(p, p) * 26 + j] + g_T3[pidx(p, j) * 26 + p];
            else if (q == j)
                v = g_T3[pidx(p, q) * 26 + q] + g_T3[pidx(q, q) * 26 + p];
            else
                v = g_T3[pidx(p, q) * 26 + j] + g_T3[pidx(p, j) * 26 + q]
                  + g_T3[pidx(q, j) * 26 + p];
            int q0 = q & ~3;
            ((float*)g_Tc4)[g_runofs[pidx(p, q)] * 4 + (j - q0)] = v;
        } else if (t < NTRI + 26) {
            int j = t - NTRI;
            float s = 0.f;
            #pragma unroll 4
            for (int i = 0; i < 128; i++) s = fmaf(g_V[i * 26 + j], b0cin[i], s);
            g_vb[j] = s;
        }
        return;
    }
    // mlp2: (4096 x 256)@(256 x 128), relu, f32x2, BM64 BN64
    float* As = (float*)smem;
    ull*   Bs = (ull*)(smem + 8192);
    int b0 = (blk >> 1) * 64, n0 = (blk & 1) * 64;
    int arow = tid & 63, kq = tid >> 6;
    int r0 = (tid & 15) * 4;
    int c0 = (tid >> 4) * 4;
    ull acc[2][4];
    #pragma unroll
    for (int i = 0; i < 2; i++)
        #pragma unroll
        for (int c = 0; c < 4; c++) acc[i][c] = 0ull;

    for (int k0 = 0; k0 < 256; k0 += 32) {
        #pragma unroll
        for (int i = 0; i < 2; i++) {
            int kb = kq * 4 + i * 16;
            float4 v = *(const float4*)&g_h1[(b0 + arow) * 256 + k0 + kb];
            As[(kb + 0) * 64 + arow] = v.x;
            As[(kb + 1) * 64 + arow] = v.y;
            As[(kb + 2) * 64 + arow] = v.z;
            As[(kb + 3) * 64 + arow] = v.w;
        }
        #pragma unroll
        for (int i = 0; i < 2; i++) {
            int t4 = tid + i * 256;
            int kk = t4 >> 4, c4 = t4 & 15;
            float4 w = *(const float4*)&W2[(k0 + kk) * 128 + n0 + c4 * 4];
            ulonglong2 d0 = {pk2(w.x, w.x), pk2(w.y, w.y)};
            ulonglong2 d1 = {pk2(w.z, w.z), pk2(w.w, w.w)};
            *(ulonglong2*)&Bs[kk * 64 + c4 * 4] = d0;
            *(ulonglong2*)&Bs[kk * 64 + c4 * 4 + 2] = d1;
        }
        __syncthreads();
        #pragma unroll
        for (int kk = 0; kk < 32; kk++) {
            ulonglong2 av = *(const ulonglong2*)&As[kk * 64 + r0];
            ulonglong2 bv0 = *(const ulonglong2*)&Bs[kk * 64 + c0];
            ulonglong2 bv1 = *(const ulonglong2*)&Bs[kk * 64 + c0 + 2];
            acc[0][0] = fma2(av.x, bv0.x, acc[0][0]);
            acc[0][1] = fma2(av.x, bv0.y, acc[0][1]);
            acc[0][2] = fma2(av.x, bv1.x, acc[0][2]);
            acc[0][3] = fma2(av.x, bv1.y, acc[0][3]);
            acc[1][0] = fma2(av.y, bv0.x, acc[1][0]);
            acc[1][1] = fma2(av.y, bv0.y, acc[1][1]);
            acc[1][2] = fma2(av.y, bv1.x, acc[1][2]);
            acc[1][3] = fma2(av.y, bv1.y, acc[1][3]);
        }
        __syncthreads();
    }
    float4 bb = *(const float4*)&b2[n0 + c0];
    #pragma unroll
    for (int rp = 0; rp < 2; rp++) {
        float2 x0 = up2(acc[rp][0]), x1 = up2(acc[rp][1]);
        float2 x2 = up2(acc[rp][2]), x3 = up2(acc[rp][3]);
        int row = b0 + r0 + rp * 2;
        float4 o0 = {fmaxf(x0.x + bb.x, 0.f), fmaxf(x1.x + bb.y, 0.f),
                     fmaxf(x2.x + bb.z, 0.f), fmaxf(x3.x + bb.w, 0.f)};
        float4 o1 = {fmaxf(x0.y + bb.x, 0.f), fmaxf(x1.y + bb.y, 0.f),
                     fmaxf(x2.y + bb.z, 0.f), fmaxf(x3.y + bb.w, 0.f)};
        *(float4*)&g_h2[row * 128 + n0 + c0] = o0;
        *(float4*)&g_h2[(row + 1) * 128 + n0 + c0] = o1;
    }
}

// ================= K4: cin f32x2-packed (warps 0..7) || final-MLP (warps 8..11)
// 384 threads, 128 blocks, 32 samples per block.
// cin thread = (sample bl 0..31, parity h, k-pair kp 0..3); lanes of f32x2 carry
// k=kp and k=kp+4. Coeffs pre-duplicated in smem.
// smem: Tcd @0 (35872), V0d @35872 (2808), vbd @38680 (208), part @38888 (512),
//       dsh @39400 (128) -> 39528 B
__global__ __launch_bounds__(384, 1) void k_final(const float* __restrict__ W3,
                                                  const float* __restrict__ b3,
                                                  const float* __restrict__ W4,
                                                  const float* __restrict__ b4,
                                                  const float* __restrict__ clinb,
                                                  float* __restrict__ out) {
    __shared__ __align__(16) unsigned char smem[39528];
    ull*    Tcd  = (ull*)smem;
    ull*    V0d  = (ull*)(smem + 35872);
    ull*    vbd  = (ull*)(smem + 38680);
    float2* part = (float2*)(smem + 38888);
    float*  dsh  = (float*)(smem + 39400);
    int tid = threadIdx.x;
    int b0 = blockIdx.x * 32;

    for (int t = tid; t < NT4; t += 384) {
        float4 tc = g_Tc4[t];
        ulonglong2 da = {pk2(tc.x, tc.x), pk2(tc.y, tc.y)};
        ulonglong2 db = {pk2(tc.z, tc.z), pk2(tc.w, tc.w)};
        *(ulonglong2*)&Tcd[t * 4] = da;
        *(ulonglong2*)&Tcd[t * 4 + 2] = db;
    }
    for (int t = tid; t < NPAIR2; t += 384) {
        float v = g_V0c[t];
        V0d[t] = pk2(v, v);
    }
    if (tid < 26) {
        float v = g_vb[tid];
        vbd[tid] = pk2(v, v);
    }
    __syncthreads();

    int w = tid >> 5, l = tid & 31;
    if (w < 8) {
        // ---- CIN, f32x2 packed ----
        int h = w >> 2;
        int bl = ((w & 3) << 3) | (l >> 2);   // 0..31
        int kp = l & 3;
        const float* eb = g_X + (b0 + bl) * XDIM + 16;
        ull e2[28];
        #pragma unroll
        for (int j = 0; j < 26; j++)
            e2[j] = pk2(eb[j * 8 + kp], eb[j * 8 + kp + 4]);
        e2[26] = 0ull; e2[27] = 0ull;

        ull s1p = 0ull, s2p = 0ull;
        if (h == 0) {
            int t4 = 0, t2 = 0;
            #pragma unroll
            for (int pp = 0; pp < 13; pp++) {
                const int p = 2 * pp;
                #pragma unroll
                for (int q = p; q < 26; q++) {
                    ull wv = mul2(e2[p], e2[q]);
                    s1p = fma2(V0d[t2], wv, s1p); t2++;
                    ull d0 = 0ull, d1 = 0ull;
                    #pragma unroll
                    for (int j4 = (q & ~3); j4 < 28; j4 += 4) {
                        ulonglong2 ta = *(const ulonglong2*)&Tcd[t4 * 4];
                        ulonglong2 tb = *(const ulonglong2*)&Tcd[t4 * 4 + 2];
                        t4++;
                        d0 = fma2(ta.x, e2[j4 + 0], d0);
                        d1 = fma2(ta.y, e2[j4 + 1], d1);
                        d0 = fma2(tb.x, e2[j4 + 2], d0);
                        d1 = fma2(tb.y, e2[j4 + 3], d1);
                    }
                    s2p = fma2(wv, add2(d0, d1), s2p);
                }
            }
            #pragma unroll
            for (int j = 0; j < 26; j++) s2p = fma2(vbd[j], e2[j], s2p);
        } else {
            int t4 = T4E, t2 = T2E;
            #pragma unroll
            for (int pp = 0; pp < 13; pp++) {
                const int p = 2 * pp + 1;
                #pragma unroll
                for (int q = p; q < 26; q++) {
                    ull wv = mul2(e2[p], e2[q]);
                    s1p = fma2(V0d[t2], wv, s1p); t2++;
                    ull d0 = 0ull, d1 = 0ull;
                    #pragma unroll
                    for (int j4 = (q & ~3); j4 < 28; j4 += 4) {
                        ulonglong2 ta = *(const ulonglong2*)&Tcd[t4 * 4];
                        ulonglong2 tb = *(const ulonglong2*)&Tcd[t4 * 4 + 2];
                        t4++;
                        d0 = fma2(ta.x, e2[j4 + 0], d0);
                        d1 = fma2(ta.y, e2[j4 + 1], d1);
                        d0 = fma2(tb.x, e2[j4 + 2], d0);
                        d1 = fma2(tb.y, e2[j4 + 3], d1);
                    }
                    s2p = fma2(wv, add2(d0, d1), s2p);
                }
            }
        }
        float2 s1u = up2(s1p), s2u = up2(s2p);
        float s1 = s1u.x + s1u.y;
        float s2 = s2u.x + s2u.y;
        #pragma unroll
        for (int off = 2; off; off >>= 1) {
            s1 += __shfl_down_sync(0xffffffffu, s1, off, 4);
            s2 += __shfl_down_sync(0xffffffffu, s2, off, 4);
        }
        if (kp == 0) part[bl * 2 + h] = make_float2(s1, s2);
    } else {
        // ---- final MLP: L3 (128->64) + L4 (64->1), warp per sample, 8 samples ----
        int wf = w - 8;
        float b3a = b3[l], b3b = b3[l + 32];
        float w4a = W4[l], w4b = W4[l + 32];
        #pragma unroll
        for (int ss = 0; ss < 8; ss++) {
            int s = wf * 8 + ss;
            const float* hrow = g_h2 + (size_t)(b0 + s) * 128;
            float aa = 0.f, ab = 0.f;
            #pragma unroll 4
            for (int k = 0; k < 128; k++) {
                float hv = __ldg(&hrow[k]);
                aa = fmaf(hv, __ldg(&W3[k * 64 + l]), aa);
                ab = fmaf(hv, __ldg(&W3[k * 64 + 32 + l]), ab);
            }
            float p = fmaxf(aa + b3a, 0.f) * w4a + fmaxf(ab + b3b, 0.f) * w4b;
            #pragma unroll
            for (int off = 16; off; off >>= 1)
                p += __shfl_down_sync(0xffffffffu, p, off);
            if (l == 0) dsh[s] = fmaxf(p + b4[0], 0.f);
        }
    }
    __syncthreads();
    if (tid < 32) {
        float2 a = part[tid * 2], b = part[tid * 2 + 1];
        int bg = b0 + tid;
        float cin = fmaxf(a.x + b.x + a.y + b.y + g_cadd + clinb[0], 0.f);
        float logit = g_lin[bg] + cin + dsh[tid];
        out[bg] = 1.f / (1.f + expf(-logit));
    }
}

// ---------------- launch: 4 serial kernels ----------------
extern "C" void kernel_launch(void* const* d_in, const int* in_sizes, int n_in,
                              void* d_out, int out_size) {
    const float* inputs     = (const float*)d_in[0];
    const float* emb_tables = (const float*)d_in[1];
    const float* linear_W   = (const float*)d_in[2];
    const float* linear_b   = (const float*)d_in[3];
    const float* W_cin0     = (const float*)d_in[4];
    const float* b_cin0     = (const float*)d_in[5];
    const float* W_cin1     = (const float*)d_in[6];
    const float* b_cin1     = (const float*)d_in[7];
    const float* cin_lin_W  = (const float*)d_in[8];
    const float* cin_lin_b  = (const float*)d_in[9];
    const float* d_W1       = (const float*)d_in[10];
    const float* d_b1       = (const float*)d_in[11];
    const float* d_W2       = (const float*)d_in[12];
    const float* d_b2       = (const float*)d_in[13];
    const float* d_W3       = (const float*)d_in[14];
    const float* d_b3       = (const float*)d_in[15];
    const float* d_W4       = (const float*)d_in[16];
    const float* d_b4       = (const float*)d_in[17];
    float* out = (float*)d_out;

    k_front<<<464, 256>>>(inputs, emb_tables, linear_W, linear_b,
                          W_cin1, cin_lin_W, b_cin0, b_cin1);
    k_mid<<<300, 256>>>(d_W1, d_b1, W_cin0, cin_lin_W);
    k_back<<<141, 256>>>(d_W2, d_b2, b_cin0);
    k_final<<<128, 384>>>(d_W3, d_b3, d_W4, d_b4, cin_lin_b, out);
}

// round 14
// speedup vs baseline: 1.2975x; 1.2975x over previous
#include <cuda_runtime.h>
#include <math.h>

#define BATCH   4096
#define VOCAB   100000
#define NTRI    3276
#define NPAIR2  351
#define NT4     1121
#define T4E     588     // float4-runs in even-p rows (parity-ordered layout)
#define T2E     182     // pairs in even-p rows
#define XDIM    224     // [0:13] dense, [13:16] zero pad, [16:224] emb (26*8)

typedef unsigned long long ull;

// ---------------- scratch (device globals) ----------------
__device__ __align__(16) float g_V[128 * 26];
__device__ __align__(16) float g_V0c[NPAIR2];    // parity-ordered
__device__ __align__(16) float g_T3[NPAIR2 * 26];
__device__ __align__(16) float4 g_Tc4[NT4];      // parity-ordered
__device__ int   g_runofs[NPAIR2];               // parity-ordered run offsets
__device__ __align__(16) float g_vb[32];
__device__ float g_cadd;
__device__ __align__(16) float g_X[BATCH * XDIM];
__device__ float g_lin[BATCH];
__device__ __align__(16) float g_h1[BATCH * 256];
__device__ __align__(16) float g_h2[BATCH * 128];

// ---------------- packed f32x2 helpers ----------------
__device__ __forceinline__ ull pk2(float lo, float hi) {
    ull r;
    asm("mov.b64 %0, {%1, %2};" : "=l"(r) : "f"(lo), "f"(hi));
    return r;
}
__device__ __forceinline__ ull fma2(ull a, ull b, ull c) {
    ull d;
    asm("fma.rn.f32x2 %0, %1, %2, %3;" : "=l"(d) : "l"(a), "l"(b), "l"(c));
    return d;
}
__device__ __forceinline__ float2 up2(ull v) {
    float2 f;
    asm("mov.b64 {%0, %1}, %2;" : "=f"(f.x), "=f"(f.y) : "l"(v));
    return f;
}
__device__ __forceinline__ int pidx(int a, int b) {
    return a * 26 - a * (a - 1) / 2 + (b - a);
}

// ================= K1: gather (blocks 0..431)  ||  prepV (blocks 432..463) =====
__global__ __launch_bounds__(256) void k_front(const float* __restrict__ inputs,
                                               const float* __restrict__ emb_tables,
                                               const float* __restrict__ linW,
                                               const float* __restrict__ linb,
                                               const float* __restrict__ W1,
                                               const float* __restrict__ clinW,
                                               const float* __restrict__ b0,
                                               const float* __restrict__ b1) {
    int bx = blockIdx.x;
    if (bx < 416) {
        int t = bx * 256 + threadIdx.x;
        int b = t / 26, f = t - b * 26;
        int idx = (int)inputs[b * 39 + 13 + f];
        const float4* src = (const float4*)(emb_tables + ((size_t)f * VOCAB + idx) * 8);
        float4* dst = (float4*)(g_X + b * XDIM + 16 + f * 8);
        dst[0] = src[0];
        dst[1] = src[1];
    } else if (bx < 432) {
        int b = (bx - 416) * 256 + threadIdx.x;
        const float* row = inputs + b * 39;
        float lin = linb[0];
        #pragma unroll
        for (int k = 0; k < 13; k++) {
            float v = row[k];
            g_X[b * XDIM + k] = v;
            lin = fmaf(v, linW[k], lin);
        }
        g_X[b * XDIM + 13] = 0.f;
        g_X[b * XDIM + 14] = 0.f;
        g_X[b * XDIM + 15] = 0.f;
        #pragma unroll
        for (int k = 13; k < 39; k++) lin = fmaf(row[k], linW[k], lin);
        g_lin[b] = lin;
    } else {
        int t0 = (bx - 432) * 256 + threadIdx.x;
        const int st = 32 * 256;
        float* tc4f = (float*)g_Tc4;
        for (int u = t0; u < NT4 * 4; u += st) tc4f[u] = 0.f;
        for (int u = t0; u < 3328; u += st) {
            float s0 = 0.f, s1 = 0.f, s2 = 0.f, s3 = 0.f;
            #pragma unroll 8
            for (int o = 0; o < 128; o += 4) {
                s0 = fmaf(clinW[128 + o + 0], W1[(o + 0) * 3328 + u], s0);
                s1 = fmaf(clinW[128 + o + 1], W1[(o + 1) * 3328 + u], s1);
                s2 = fmaf(clinW[128 + o + 2], W1[(o + 2) * 3328 + u], s2);
                s3 = fmaf(clinW[128 + o + 3], W1[(o + 3) * 3328 + u], s3);
            }
            g_V[u] = (s0 + s1) + (s2 + s3);
        }
        for (int t2 = t0; t2 < NPAIR2; t2 += st) {
            int p = 0, rem = t2;
            while (rem >= 26 - p) { rem -= 26 - p; p++; }
            int q = p + rem;
            int s4 = (p & 1) ? T4E : 0;
            for (int pp = (p & 1); pp < p; pp += 2)
                for (int qq = pp; qq < 26; qq++) s4 += 7 - (qq >> 2);
            for (int qq = p; qq < q; qq++) s4 += 7 - (qq >> 2);
            g_runofs[t2] = s4;
        }
        if (t0 < 32) {
            float s = 0.f;
            for (int o = t0; o < 128; o += 32)
                s += clinW[o] * b0[o] + clinW[128 + o] * b1[o];
            #pragma unroll
            for (int off = 16; off; off >>= 1) s += __shfl_down_sync(0xffffffffu, s, off);
            if (t0 == 0) g_cadd = 8.f * s;
        }
    }
}

// ================= K2: mlp1 (blocks 0..255)  ||  prepT3+V0c (blocks 256..299) ===
__global__ __launch_bounds__(256) void k_mid(const float* __restrict__ W1,
                                             const float* __restrict__ b1,
                                             const float* __restrict__ W0,
                                             const float* __restrict__ clinW) {
    __shared__ __align__(16) unsigned char smem[24576];
    int blk = blockIdx.x;
    int tid = threadIdx.x;
    if (blk >= 256) {
        int pq = (blk - 256) * 8 + (tid >> 5);
        if (pq >= NPAIR2) return;
        int p = 0, rem = pq;
        while (rem >= 26 - p) { rem -= 26 - p; p++; }
        int q = p + rem;
        int j = tid & 31;
        const float* wp = W0 + p * 26 + q;
        const float* wq = W0 + q * 26 + p;
        bool isV = (j == 26);
        bool isT = (j < 26);
        float a0 = 0.f, a1 = 0.f, a2 = 0.f, a3 = 0.f;
        if (p == q) {
            #pragma unroll 4
            for (int i = 0; i < 128; i += 4) {
                float w0 = __ldg(&wp[(i + 0) * 676]);
                float w1 = __ldg(&wp[(i + 1) * 676]);
                float w2 = __ldg(&wp[(i + 2) * 676]);
                float w3 = __ldg(&wp[(i + 3) * 676]);
                float v0 = isT ? g_V[(i + 0) * 26 + j] : (isV ? clinW[i + 0] : 0.f);
                float v1 = isT ? g_V[(i + 1) * 26 + j] : (isV ? clinW[i + 1] : 0.f);
                float v2 = isT ? g_V[(i + 2) * 26 + j] : (isV ? clinW[i + 2] : 0.f);
                float v3 = isT ? g_V[(i + 3) * 26 + j] : (isV ? clinW[i + 3] : 0.f);
                a0 = fmaf(w0, v0, a0); a1 = fmaf(w1, v1, a1);
                a2 = fmaf(w2, v2, a2); a3 = fmaf(w3, v3, a3);
            }
        } else {
            #pragma unroll 4
            for (int i = 0; i < 128; i += 4) {
                float w0 = __ldg(&wp[(i + 0) * 676]) + __ldg(&wq[(i + 0) * 676]);
                float w1 = __ldg(&wp[(i + 1) * 676]) + __ldg(&wq[(i + 1) * 676]);
                float w2 = __ldg(&wp[(i + 2) * 676]) + __ldg(&wq[(i + 2) * 676]);
                float w3 = __ldg(&wp[(i + 3) * 676]) + __ldg(&wq[(i + 3) * 676]);
                float v0 = isT ? g_V[(i + 0) * 26 + j] : (isV ? clinW[i + 0] : 0.f);
                float v1 = isT ? g_V[(i + 1) * 26 + j] : (isV ? clinW[i + 1] : 0.f);
                float v2 = isT ? g_V[(i + 2) * 26 + j] : (isV ? clinW[i + 2] : 0.f);
                float v3 = isT ? g_V[(i + 3) * 26 + j] : (isV ? clinW[i + 3] : 0.f);
                a0 = fmaf(w0, v0, a0); a1 = fmaf(w1, v1, a1);
                a2 = fmaf(w2, v2, a2); a3 = fmaf(w3, v3, a3);
            }
        }
        float s = (a0 + a1) + (a2 + a3);
        if (isT) g_T3[pq * 26 + j] = s;
        else if (isV) {
            int t2pos = (p & 1) ? T2E : 0;
            for (int pp = (p & 1); pp < p; pp += 2) t2pos += 26 - pp;
            t2pos += q - p;
            g_V0c[t2pos] = s;
        }
        return;
    }
    // mlp1: (4096 x 224)@(224 x 256), relu, f32x2, BM64 BN64
    float* As = (float*)smem;
    ull*   Bs = (ull*)(smem + 8192);
    int b0 = (blk >> 2) * 64, n0 = (blk & 3) * 64;
    int arow = tid & 63, kq = tid >> 6;
    int r0 = (tid & 15) * 4;
    int c0 = (tid >> 4) * 4;
    ull acc[2][4];
    #pragma unroll
    for (int i = 0; i < 2; i++)
        #pragma unroll
        for (int c = 0; c < 4; c++) acc[i][c] = 0ull;

    for (int k0 = 0; k0 < XDIM; k0 += 32) {
        #pragma unroll
        for (int i = 0; i < 2; i++) {
            int kb = kq * 4 + i * 16;
            float4 v = *(const float4*)&g_X[(b0 + arow) * XDIM + k0 + kb];
            As[(kb + 0) * 64 + arow] = v.x;
            As[(kb + 1) * 64 + arow] = v.y;
            As[(kb + 2) * 64 + arow] = v.z;
            As[(kb + 3) * 64 + arow] = v.w;
        }
        #pragma unroll
        for (int i = 0; i < 2; i++) {
            int t4 = tid + i * 256;
            int kk = t4 >> 4, c4 = t4 & 15;
            int krow = k0 + kk;
            float4 w = make_float4(0.f, 0.f, 0.f, 0.f);
            if (krow < 13)       w = *(const float4*)&W1[krow * 256 + n0 + c4 * 4];
            else if (krow >= 16) w = *(const float4*)&W1[(krow - 3) * 256 + n0 + c4 * 4];
            ulonglong2 d0 = {pk2(w.x, w.x), pk2(w.y, w.y)};
            ulonglong2 d1 = {pk2(w.z, w.z), pk2(w.w, w.w)};
            *(ulonglong2*)&Bs[kk * 64 + c4 * 4] = d0;
            *(ulonglong2*)&Bs[kk * 64 + c4 * 4 + 2] = d1;
        }
        __syncthreads();
        #pragma unroll
        for (int kk = 0; kk < 32; kk++) {
            ulonglong2 av = *(const ulonglong2*)&As[kk * 64 + r0];
            ulonglong2 bv0 = *(const ulonglong2*)&Bs[kk * 64 + c0];
            ulonglong2 bv1 = *(const ulonglong2*)&Bs[kk * 64 + c0 + 2];
            acc[0][0] = fma2(av.x, bv0.x, acc[0][0]);
            acc[0][1] = fma2(av.x, bv0.y, acc[0][1]);
            acc[0][2] = fma2(av.x, bv1.x, acc[0][2]);
            acc[0][3] = fma2(av.x, bv1.y, acc[0][3]);
            acc[1][0] = fma2(av.y, bv0.x, acc[1][0]);
            acc[1][1] = fma2(av.y, bv0.y, acc[1][1]);
            acc[1][2] = fma2(av.y, bv1.x, acc[1][2]);
            acc[1][3] = fma2(av.y, bv1.y, acc[1][3]);
        }
        __syncthreads();
    }
    float4 bb = *(const float4*)&b1[n0 + c0];
    #pragma unroll
    for (int rp = 0; rp < 2; rp++) {
        float2 x0 = up2(acc[rp][0]), x1 = up2(acc[rp][1]);
        float2 x2 = up2(acc[rp][2]), x3 = up2(acc[rp][3]);
        int row = b0 + r0 + rp * 2;
        float4 o0 = {fmaxf(x0.x + bb.x, 0.f), fmaxf(x1.x + bb.y, 0.f),
                     fmaxf(x2.x + bb.z, 0.f), fmaxf(x3.x + bb.w, 0.f)};
        float4 o1 = {fmaxf(x0.y + bb.x, 0.f), fmaxf(x1.y + bb.y, 0.f),
                     fmaxf(x2.y + bb.z, 0.f), fmaxf(x3.y + bb.w, 0.f)};
        *(float4*)&g_h1[row * 256 + n0 + c0] = o0;
        *(float4*)&g_h1[(row + 1) * 256 + n0 + c0] = o1;
    }
}

// ================= K3: mlp2 (blocks 0..127)  ||  prepFold (blocks 128..140) =====
__global__ __launch_bounds__(256) void k_back(const float* __restrict__ W2,
                                              const float* __restrict__ b2,
                                              const float* __restrict__ b0cin) {
    __shared__ __align__(16) unsigned char smem[24576];
    int blk = blockIdx.x;
    int tid = threadIdx.x;
    if (blk >= 128) {
        int t = (blk - 128) * 256 + tid;
        if (t < NTRI) {
            int rem = t, p = 0;
            while (true) { int c = (26 - p) * (27 - p) / 2; if (rem < c) break; rem -= c; p++; }
            int q = p;
            while (true) { int c = 26 - q; if (rem < c) break; rem -= c; q++; }
            int j = q + rem;
            float v;
            if (p == q && q == j)
                v = g_T3[pidx(p, p) * 26 + p];
            else if (p == q)
                v = g_T3[pidx(p, p) * 26 + j] + g_T3[pidx(p, j) * 26 + p];
            else if (q == j)
                v = g_T3[pidx(p, q) * 26 + q] + g_T3[pidx(q, q) * 26 + p];
            else
                v = g_T3[pidx(p, q) * 26 + j] + g_T3[pidx(p, j) * 26 + q]
                  + g_T3[pidx(q, j) * 26 + p];
            int q0 = q & ~3;
            ((float*)g_Tc4)[g_runofs[pidx(p, q)] * 4 + (j - q0)] = v;
        } else if (t < NTRI + 26) {
            int j = t - NTRI;
            float s = 0.f;
            #pragma unroll 4
            for (int i = 0; i < 128; i++) s = fmaf(g_V[i * 26 + j], b0cin[i], s);
            g_vb[j] = s;
        }
        return;
    }
    // mlp2: (4096 x 256)@(256 x 128), relu, f32x2, BM64 BN64
    float* As = (float*)smem;
    ull*   Bs = (ull*)(smem + 8192);
    int b0 = (blk >> 1) * 64, n0 = (blk & 1) * 64;
    int arow = tid & 63, kq = tid >> 6;
    int r0 = (tid & 15) * 4;
    int c0 = (tid >> 4) * 4;
    ull acc[2][4];
    #pragma unroll
    for (int i = 0; i < 2; i++)
        #pragma unroll
        for (int c = 0; c < 4; c++) acc[i][c] = 0ull;

    for (int k0 = 0; k0 < 256; k0 += 32) {
        #pragma unroll
        for (int i = 0; i < 2; i++) {
            int kb = kq * 4 + i * 16;
            float4 v = *(const float4*)&g_h1[(b0 + arow) * 256 + k0 + kb];
            As[(kb + 0) * 64 + arow] = v.x;
            As[(kb + 1) * 64 + arow] = v.y;
            As[(kb + 2) * 64 + arow] = v.z;
            As[(kb + 3) * 64 + arow] = v.w;
        }
        #pragma unroll
        for (int i = 0; i < 2; i++) {
            int t4 = tid + i * 256;
            int kk = t4 >> 4, c4 = t4 & 15;
            float4 w = *(const float4*)&W2[(k0 + kk) * 128 + n0 + c4 * 4];
            ulonglong2 d0 = {pk2(w.x, w.x), pk2(w.y, w.y)};
            ulonglong2 d1 = {pk2(w.z, w.z), pk2(w.w, w.w)};
            *(ulonglong2*)&Bs[kk * 64 + c4 * 4] = d0;
            *(ulonglong2*)&Bs[kk * 64 + c4 * 4 + 2] = d1;
        }
        __syncthreads();
        #pragma unroll
        for (int kk = 0; kk < 32; kk++) {
            ulonglong2 av = *(const ulonglong2*)&As[kk * 64 + r0];
            ulonglong2 bv0 = *(const ulonglong2*)&Bs[kk * 64 + c0];
            ulonglong2 bv1 = *(const ulonglong2*)&Bs[kk * 64 + c0 + 2];
            acc[0][0] = fma2(av.x, bv0.x, acc[0][0]);
            acc[0][1] = fma2(av.x, bv0.y, acc[0][1]);
            acc[0][2] = fma2(av.x, bv1.x, acc[0][2]);
            acc[0][3] = fma2(av.x, bv1.y, acc[0][3]);
            acc[1][0] = fma2(av.y, bv0.x, acc[1][0]);
            acc[1][1] = fma2(av.y, bv0.y, acc[1][1]);
            acc[1][2] = fma2(av.y, bv1.x, acc[1][2]);
            acc[1][3] = fma2(av.y, bv1.y, acc[1][3]);
        }
        __syncthreads();
    }
    float4 bb = *(const float4*)&b2[n0 + c0];
    #pragma unroll
    for (int rp = 0; rp < 2; rp++) {
        float2 x0 = up2(acc[rp][0]), x1 = up2(acc[rp][1]);
        float2 x2 = up2(acc[rp][2]), x3 = up2(acc[rp][3]);
        int row = b0 + r0 + rp * 2;
        float4 o0 = {fmaxf(x0.x + bb.x, 0.f), fmaxf(x1.x + bb.y, 0.f),
                     fmaxf(x2.x + bb.z, 0.f), fmaxf(x3.x + bb.w, 0.f)};
        float4 o1 = {fmaxf(x0.y + bb.x, 0.f), fmaxf(x1.y + bb.y, 0.f),
                     fmaxf(x2.y + bb.z, 0.f), fmaxf(x3.y + bb.w, 0.f)};
        *(float4*)&g_h2[row * 128 + n0 + c0] = o0;
        *(float4*)&g_h2[(row + 1) * 128 + n0 + c0] = o1;
    }
}

// ================= K4: cin (warps 0..7) || final-MLP (warps 8..11) + combine ====
// 384 threads, 256 blocks, 16 samples per block.
// smem: hs @0 (8192), Tc4s @8192 (17936), V0s @26128 (1404), vbs @27536 (128),
//       part @27664 (256), dsh @27920 (64) -> 27984 B
__global__ __launch_bounds__(384) void k_final(const float* __restrict__ W3,
                                               const float* __restrict__ b3,
                                               const float* __restrict__ W4,
                                               const float* __restrict__ b4,
                                               const float* __restrict__ clinb,
                                               float* __restrict__ out) {
    __shared__ __align__(16) unsigned char smem[27984];
    float*  hs   = (float*)smem;
    float4* Tc4s = (float4*)(smem + 8192);
    float*  V0s  = (float*)(smem + 26128);
    float*  vbs  = (float*)(smem + 27536);
    float2* part = (float2*)(smem + 27664);
    float*  dsh  = (float*)(smem + 27920);
    int tid = threadIdx.x;
    int b0 = blockIdx.x * 16;

    for (int t = tid; t < 512; t += 384)
        ((float4*)hs)[t] = ((const float4*)(g_h2 + b0 * 128))[t];
    for (int t = tid; t < NT4; t += 384) Tc4s[t] = g_Tc4[t];
    for (int t = tid; t < NPAIR2; t += 384) V0s[t] = g_V0c[t];
    if (tid < 26) vbs[tid] = g_vb[tid];

    int w = tid >> 5, l = tid & 31;
    if (w < 8) {
        // ---- CIN (parity-split, 4 independent run accumulators) ----
        int h = w >> 2;
        int bl = ((w & 3) << 2) | (l >> 3);
        int k = l & 7;
        const float* eb = g_X + (b0 + bl) * XDIM + 16 + k;
        float e[28];
        #pragma unroll
        for (int j = 0; j < 26; j++) e[j] = eb[j * 8];
        e[26] = 0.f; e[27] = 0.f;
        __syncthreads();

        float s1p = 0.f, s2p = 0.f;
        if (h == 0) {
            int t4 = 0, t2 = 0;
            #pragma unroll
            for (int pp = 0; pp < 13; pp++) {
                const int p = 2 * pp;
                #pragma unroll
                for (int q = p; q < 26; q++) {
                    float wv = e[p] * e[q];
                    s1p = fmaf(V0s[t2], wv, s1p); t2++;
                    float d0 = 0.f, d1 = 0.f, d2 = 0.f, d3 = 0.f;
                    #pragma unroll
                    for (int j4 = (q & ~3); j4 < 28; j4 += 4) {
                        float4 tc = Tc4s[t4]; t4++;
                        d0 = fmaf(tc.x, e[j4 + 0], d0);
                        d1 = fmaf(tc.y, e[j4 + 1], d1);
                        d2 = fmaf(tc.z, e[j4 + 2], d2);
                        d3 = fmaf(tc.w, e[j4 + 3], d3);
                    }
                    s2p = fmaf(wv, (d0 + d1) + (d2 + d3), s2p);
                }
            }
            #pragma unroll
            for (int j = 0; j < 26; j++) s2p = fmaf(vbs[j], e[j], s2p);
        } else {
            int t4 = T4E, t2 = T2E;
            #pragma unroll
            for (int pp = 0; pp < 13; pp++) {
                const int p = 2 * pp + 1;
                #pragma unroll
                for (int q = p; q < 26; q++) {
                    float wv = e[p] * e[q];
                    s1p = fmaf(V0s[t2], wv, s1p); t2++;
                    float d0 = 0.f, d1 = 0.f, d2 = 0.f, d3 = 0.f;
                    #pragma unroll
                    for (int j4 = (q & ~3); j4 < 28; j4 += 4) {
                        float4 tc = Tc4s[t4]; t4++;
                        d0 = fmaf(tc.x, e[j4 + 0], d0);
                        d1 = fmaf(tc.y, e[j4 + 1], d1);
                        d2 = fmaf(tc.z, e[j4 + 2], d2);
                        d3 = fmaf(tc.w, e[j4 + 3], d3);
                    }
                    s2p = fmaf(wv, (d0 + d1) + (d2 + d3), s2p);
                }
            }
        }
        #pragma unroll
        for (int off = 4; off; off >>= 1) {
            s1p += __shfl_down_sync(0xffffffffu, s1p, off, 8);
            s2p += __shfl_down_sync(0xffffffffu, s2p, off, 8);
        }
        if (k == 0) part[bl * 2 + h] = make_float2(s1p, s2p);
    } else {
        // ---- final MLP: L3 (128->64) + L4 (64->1), warp per sample ----
        __syncthreads();   // matches cin half's barrier (hs ready)
        int wf = w - 8;
        float b3a = b3[l], b3b = b3[l + 32];
        float w4a = W4[l], w4b = W4[l + 32];
        #pragma unroll
        for (int ss = 0; ss < 4; ss++) {
            int s = wf * 4 + ss;
            float aa = 0.f, ab = 0.f;
            #pragma unroll 4
            for (int k = 0; k < 128; k++) {
                float hv = hs[s * 128 + k];
                aa = fmaf(hv, __ldg(&W3[k * 64 + l]), aa);
                ab = fmaf(hv, __ldg(&W3[k * 64 + 32 + l]), ab);
            }
            float p = fmaxf(aa + b3a, 0.f) * w4a + fmaxf(ab + b3b, 0.f) * w4b;
            #pragma unroll
            for (int off = 16; off; off >>= 1)
                p += __shfl_down_sync(0xffffffffu, p, off);
            if (l == 0) dsh[s] = fmaxf(p + b4[0], 0.f);
        }
    }
    __syncthreads();
    if (tid < 16) {
        float2 a = part[tid * 2], b = part[tid * 2 + 1];
        int bg = b0 + tid;
        float cin = fmaxf(a.x + b.x + a.y + b.y + g_cadd + clinb[0], 0.f);
        float logit = g_lin[bg] + cin + dsh[tid];
        out[bg] = 1.f / (1.f + expf(-logit));
    }
}

// ---------------- launch: 4 serial kernels ----------------
extern "C" void kernel_launch(void* const* d_in, const int* in_sizes, int n_in,
                              void* d_out, int out_size) {
    const float* inputs     = (const float*)d_in[0];
    const float* emb_tables = (const float*)d_in[1];
    const float* linear_W   = (const float*)d_in[2];
    const float* linear_b   = (const float*)d_in[3];
    const float* W_cin0     = (const float*)d_in[4];
    const float* b_cin0     = (const float*)d_in[5];
    const float* W_cin1     = (const float*)d_in[6];
    const float* b_cin1     = (const float*)d_in[7];
    const float* cin_lin_W  = (const float*)d_in[8];
    const float* cin_lin_b  = (const float*)d_in[9];
    const float* d_W1       = (const float*)d_in[10];
    const float* d_b1       = (const float*)d_in[11];
    const float* d_W2       = (const float*)d_in[12];
    const float* d_b2       = (const float*)d_in[13];
    const float* d_W3       = (const float*)d_in[14];
    const float* d_b3       = (const float*)d_in[15];
    const float* d_W4       = (const float*)d_in[16];
    const float* d_b4       = (const float*)d_in[17];
    float* out = (float*)d_out;

    k_front<<<464, 256>>>(inputs, emb_tables, linear_W, linear_b,
                          W_cin1, cin_lin_W, b_cin0, b_cin1);
    k_mid<<<300, 256>>>(d_W1, d_b1, W_cin0, cin_lin_W);
    k_back<<<141, 256>>>(d_W2, d_b2, b_cin0);
    k_final<<<256, 384>>>(d_W3, d_b3, d_W4, d_b4, cin_lin_b, out);
}